// round 1
// baseline (speedup 1.0000x reference)
#include <cuda_runtime.h>
#include <math.h>

// Problem shapes (fixed by setup_inputs)
namespace {
constexpr int B_ = 2, Q_ = 75, N_ = 5, T_ = 196, C_ = 384, D_ = 384;
constexpr int CHUNK = 64;                 // c1 chunk
constexpr int NCH = C_ / CHUNK;           // 6
constexpr int TPAD = 208;                 // 196 padded to 16-multiple+
constexpr int ALD = 65;                   // attn-transposed leading dim (c1 + pad)
constexpr float SCALE = 1.0f / 14.0f;     // 1/sqrt(k*t) = 1/sqrt(196)

// shared memory layout (floats)
constexpr int OFF_ATT = 0;                        // [C_][ALD]  attn^T: [c2][c1]
constexpr int OFF_FQ  = OFF_ATT + C_ * ALD;       // [TPAD][64] FQ chunk columns
constexpr int OFF_STG = OFF_FQ + TPAD * CHUNK;    // staging: GEMM1 B tile (16x132) / GEMM2 A tile (16xTPAD)
constexpr int OFF_NUM = OFF_STG + 16 * TPAD;
constexpr int OFF_SQ  = OFF_NUM + T_;
constexpr int OFF_FSN = OFF_SQ + T_;
constexpr int SMEM_FLOATS = OFF_FSN + T_;
constexpr int SMEM_BYTES = SMEM_FLOATS * 4;       // 168,752 B
}

// One CTA per (b,q,n). blockDim = (16,16).
__global__ void __launch_bounds__(256, 1)
tok_main_kernel(const float* __restrict__ FQg,
                const float* __restrict__ FSg,
                float* __restrict__ out)
{
    extern __shared__ float sm[];
    float* sAtt = sm + OFF_ATT;
    float* sFQ  = sm + OFF_FQ;
    float* sStg = sm + OFF_STG;
    float* sNum = sm + OFF_NUM;
    float* sSq  = sm + OFF_SQ;
    float* sFsn = sm + OFF_FSN;

    const int n = blockIdx.x, q = blockIdx.y, b = blockIdx.z;
    const int tx = threadIdx.x, ty = threadIdx.y;
    const int tid = ty * 16 + tx;
    const int lane = tid & 31, wid = tid >> 5;

    const float* FQ = FQg + (size_t)(b * Q_ + q) * T_ * C_;
    const float* FS = FSg + (size_t)(b * N_ + n) * T_ * C_;
    const float4* FQ4 = reinterpret_cast<const float4*>(FQ);
    const float4* FS4 = reinterpret_cast<const float4*>(FS);

    // init accumulators
    for (int i = tid; i < T_; i += 256) { sNum[i] = 0.f; sSq[i] = 0.f; }

    // ||fs[t,:]||^2 per token
    for (int t = wid; t < T_; t += 8) {
        float s = 0.f;
        const float* row = FS + t * C_;
        for (int c = lane; c < C_; c += 32) { float v = row[c]; s = fmaf(v, v, s); }
        #pragma unroll
        for (int o = 16; o > 0; o >>= 1) s += __shfl_xor_sync(0xffffffffu, s, o);
        if (lane == 0) sFsn[t] = s;
    }
    __syncthreads();

    for (int ch = 0; ch < NCH; ++ch) {
        // ---- stage FQ chunk columns: sFQ[t][c1l], zero-padded rows ----
        for (int idx = tid; idx < TPAD * 16; idx += 256) {
            int t = idx >> 4, c4 = idx & 15;
            float4 v = make_float4(0.f, 0.f, 0.f, 0.f);
            if (t < T_) v = FQ4[t * 96 + ch * 16 + c4];
            reinterpret_cast<float4*>(sFQ)[t * 16 + c4] = v;
        }
        __syncthreads();

        // ---- GEMM1: attn[c1][c2] = sum_t FQ[t][c1]*FS[t][c2], K=196 ----
        for (int p = 0; p < 3; ++p) {       // c2 blocks of 128
            float acc[4][8];
            #pragma unroll
            for (int i = 0; i < 4; ++i)
                #pragma unroll
                for (int j = 0; j < 8; ++j) acc[i][j] = 0.f;

            for (int kk = 0; kk < T_; kk += 16) {
                // load FS tile [16][128] (row pad 132), zero-fill t>=196
                for (int idx = tid; idx < 512; idx += 256) {
                    int r = idx >> 5, c4 = idx & 31;
                    int t = kk + r;
                    float4 v = make_float4(0.f, 0.f, 0.f, 0.f);
                    if (t < T_) v = FS4[t * 96 + p * 32 + c4];
                    *reinterpret_cast<float4*>(&sStg[r * 132 + c4 * 4]) = v;
                }
                __syncthreads();
                #pragma unroll
                for (int k = 0; k < 16; ++k) {
                    float a[4], bb[8];
                    #pragma unroll
                    for (int i = 0; i < 4; ++i) a[i] = sFQ[(kk + k) * 64 + ty + 16 * i];
                    #pragma unroll
                    for (int j = 0; j < 8; ++j) bb[j] = sStg[k * 132 + tx * 8 + j];
                    #pragma unroll
                    for (int i = 0; i < 4; ++i)
                        #pragma unroll
                        for (int j = 0; j < 8; ++j) acc[i][j] = fmaf(a[i], bb[j], acc[i][j]);
                }
                __syncthreads();
            }
            // store transposed+scaled: sAtt[c2][c1]
            #pragma unroll
            for (int i = 0; i < 4; ++i)
                #pragma unroll
                for (int j = 0; j < 8; ++j)
                    sAtt[(p * 128 + tx * 8 + j) * ALD + ty + 16 * i] = acc[i][j] * SCALE;
        }
        __syncthreads();

        // ---- softmax over c2 (column of sAtt per c1), warp-per-row ----
        #pragma unroll
        for (int r = 0; r < 8; ++r) {
            int c1 = wid * 8 + r;
            float x[12];
            float mx = -1e30f;
            #pragma unroll
            for (int m = 0; m < 12; ++m) {
                x[m] = sAtt[(lane + 32 * m) * ALD + c1];
                mx = fmaxf(mx, x[m]);
            }
            #pragma unroll
            for (int o = 16; o > 0; o >>= 1) mx = fmaxf(mx, __shfl_xor_sync(0xffffffffu, mx, o));
            float s = 0.f;
            #pragma unroll
            for (int m = 0; m < 12; ++m) { x[m] = __expf(x[m] - mx); s += x[m]; }
            #pragma unroll
            for (int o = 16; o > 0; o >>= 1) s += __shfl_xor_sync(0xffffffffu, s, o);
            float inv = 1.f / s;
            #pragma unroll
            for (int m = 0; m < 12; ++m) sAtt[(lane + 32 * m) * ALD + c1] = x[m] * inv;
        }
        __syncthreads();

        // ---- GEMM2: fq_new[t][c1] = sum_c2 FQ[t][c2]*attn[c1][c2], K=384 ----
        float acc2[13][4];
        #pragma unroll
        for (int i = 0; i < 13; ++i)
            #pragma unroll
            for (int j = 0; j < 4; ++j) acc2[i][j] = 0.f;

        for (int c2b = 0; c2b < C_; c2b += 16) {
            // stage FQ K-tile transposed: sStg[k][t]
            for (int idx = tid; idx < 784; idx += 256) {
                int t = idx >> 2, g = idx & 3;
                float4 v = FQ4[t * 96 + (c2b >> 2) + g];
                sStg[(g * 4 + 0) * TPAD + t] = v.x;
                sStg[(g * 4 + 1) * TPAD + t] = v.y;
                sStg[(g * 4 + 2) * TPAD + t] = v.z;
                sStg[(g * 4 + 3) * TPAD + t] = v.w;
            }
            __syncthreads();
            #pragma unroll
            for (int k = 0; k < 16; ++k) {
                float bv[4];
                #pragma unroll
                for (int j = 0; j < 4; ++j) bv[j] = sAtt[(c2b + k) * ALD + tx * 4 + j];
                #pragma unroll
                for (int i = 0; i < 13; ++i) {
                    float av = sStg[k * TPAD + ty + 16 * i];  // rows >=196 garbage but unused
                    #pragma unroll
                    for (int j = 0; j < 4; ++j) acc2[i][j] = fmaf(av, bv[j], acc2[i][j]);
                }
            }
            __syncthreads();
        }

        // ---- fused cosine epilogue: accumulate num[t], sq[t] ----
        #pragma unroll
        for (int i = 0; i < 13; ++i) {
            int t = ty + 16 * i;
            if (t < T_) {   // warp-uniform: i<12 all, i==12 only warps with ty<4 (fully active)
                float4 fv = FS4[t * 96 + ch * 16 + tx];
                float nl = acc2[i][0] * fv.x + acc2[i][1] * fv.y
                         + acc2[i][2] * fv.z + acc2[i][3] * fv.w;
                float sl = acc2[i][0] * acc2[i][0] + acc2[i][1] * acc2[i][1]
                         + acc2[i][2] * acc2[i][2] + acc2[i][3] * acc2[i][3];
                #pragma unroll
                for (int o = 1; o < 16; o <<= 1) {
                    nl += __shfl_xor_sync(0xffffffffu, nl, o);
                    sl += __shfl_xor_sync(0xffffffffu, sl, o);
                }
                if (tx == 0) { sNum[t] += nl; sSq[t] += sl; }
            }
        }
        __syncthreads();
    }

    // ---- top-1 over t, mean over n via atomicAdd ----
    if (wid == 0) {
        float best = -1e30f;
        for (int t = lane; t < T_; t += 32) {
            float den = fmaxf(sqrtf(sSq[t] * sFsn[t]), 1e-8f);
            best = fmaxf(best, sNum[t] / den);
        }
        #pragma unroll
        for (int o = 16; o > 0; o >>= 1) best = fmaxf(best, __shfl_xor_sync(0xffffffffu, best, o));
        if (lane == 0) atomicAdd(&out[b * Q_ + q], best * (1.0f / N_));
    }
}

// prototype-cosine branch: cls[b,q,n] = 10 * <xq_hat, xs_hat>
__global__ void tok_cls_kernel(const float* __restrict__ XQ,
                               const float* __restrict__ XS,
                               float* __restrict__ out)
{
    int w = (blockIdx.x * blockDim.x + threadIdx.x) >> 5;
    int lane = threadIdx.x & 31;
    if (w >= B_ * Q_ * N_) return;
    int n = w % N_;
    int bq = w / N_;
    int q = bq % Q_;
    int b = bq / Q_;
    const float* xq = XQ + (size_t)(b * Q_ + q) * D_;
    const float* xs = XS + (size_t)(b * N_ + n) * D_;
    float dot = 0.f, nq = 0.f, ns = 0.f;
    for (int d = lane; d < D_; d += 32) {
        float a = xq[d], c = xs[d];
        dot = fmaf(a, c, dot);
        nq  = fmaf(a, a, nq);
        ns  = fmaf(c, c, ns);
    }
    #pragma unroll
    for (int o = 16; o > 0; o >>= 1) {
        dot += __shfl_xor_sync(0xffffffffu, dot, o);
        nq  += __shfl_xor_sync(0xffffffffu, nq, o);
        ns  += __shfl_xor_sync(0xffffffffu, ns, o);
    }
    if (lane == 0) {
        float denom = fmaxf(sqrtf(nq), 1e-12f) * fmaxf(sqrtf(ns), 1e-12f);
        out[B_ * Q_ + w] = 10.0f * dot / denom;
    }
}

__global__ void tok_init_kernel(float* __restrict__ out)
{
    int i = blockIdx.x * blockDim.x + threadIdx.x;
    if (i < B_ * Q_) out[i] = 0.f;
}

extern "C" void kernel_launch(void* const* d_in, const int* in_sizes, int n_in,
                              void* d_out, int out_size)
{
    const float* fq = (const float*)d_in[0];  // feat_query (2,75,196,384)
    const float* fs = (const float*)d_in[1];  // feat_shot  (2,5,1,196,384)
    const float* xq = (const float*)d_in[2];  // x_query    (2,75,384)
    const float* xs = (const float*)d_in[3];  // x_shot     (2,5,1,384)
    float* out = (float*)d_out;               // [150 logits | 750 cls_logits]

    cudaFuncSetAttribute(tok_main_kernel,
                         cudaFuncAttributeMaxDynamicSharedMemorySize, SMEM_BYTES);

    tok_init_kernel<<<1, 256>>>(out);
    tok_cls_kernel<<<(B_ * Q_ * N_ * 32 + 255) / 256, 256>>>(xq, xs, out);
    dim3 grid(N_, Q_, B_), blk(16, 16);
    tok_main_kernel<<<grid, blk, SMEM_BYTES>>>(fq, fs, out);
}

// round 2
// speedup vs baseline: 1.2536x; 1.2536x over previous
#include <cuda_runtime.h>
#include <math.h>

// Problem shapes (fixed by setup_inputs)
namespace {
constexpr int B_ = 2, Q_ = 75, N_ = 5, T_ = 196, C_ = 384, D_ = 384;
constexpr int CHUNK = 64;                 // c1 chunk
constexpr int NCH = C_ / CHUNK;           // 6
constexpr int TPQ = 224;                  // FQ chunk rows padded to 32-multiple
constexpr int ALD = 66;                   // attn-transposed leading dim (even -> 8B-aligned rows)
constexpr int LDB = 132;                  // GEMM1 FS staging row stride
constexpr int LDT = 211;                  // GEMM2 FQ^T staging row stride (odd -> conflict-free writes)
constexpr float SCALE = 1.0f / 14.0f;     // 1/sqrt(k*t) = 1/sqrt(196)

// shared memory layout (floats)
constexpr int OFF_ATT = 0;                        // [C_][ALD]   attn^T: [c2][c1local]
constexpr int OFF_FQ  = OFF_ATT + C_ * ALD;       // [TPQ][64]   FQ chunk columns
constexpr int OFF_STG = OFF_FQ + TPQ * CHUNK;     // staging: max(32*LDB, 32*LDT)
constexpr int STG_SZ  = 32 * LDT;                 // 6752 > 32*132
constexpr int OFF_NUM = OFF_STG + STG_SZ;
constexpr int OFF_SQ  = OFF_NUM + T_;
constexpr int OFF_FSN = OFF_SQ + T_;
constexpr int SMEM_FLOATS = OFF_FSN + T_;
constexpr int SMEM_BYTES = SMEM_FLOATS * 4;       // ~188 KB
}

// ---- packed f32x2 helpers (Blackwell FFMA2 path, PTX-only) ----
__device__ __forceinline__ unsigned long long pk2(float lo, float hi) {
    unsigned long long r;
    asm("mov.b64 %0, {%1, %2};" : "=l"(r) : "f"(lo), "f"(hi));
    return r;
}
__device__ __forceinline__ float2 upk2(unsigned long long v) {
    float2 r;
    asm("mov.b64 {%0, %1}, %2;" : "=f"(r.x), "=f"(r.y) : "l"(v));
    return r;
}
__device__ __forceinline__ unsigned long long fma2(unsigned long long a,
                                                   unsigned long long b,
                                                   unsigned long long c) {
    unsigned long long d;
    asm("fma.rn.f32x2 %0, %1, %2, %3;" : "=l"(d) : "l"(a), "l"(b), "l"(c));
    return d;
}

// One CTA per (b,q,n). blockDim = (16,16).
__global__ void __launch_bounds__(256, 1)
tok_main_kernel(const float* __restrict__ FQg,
                const float* __restrict__ FSg,
                float* __restrict__ out)
{
    extern __shared__ float sm[];
    float* sAtt = sm + OFF_ATT;
    float* sFQ  = sm + OFF_FQ;
    float* sStg = sm + OFF_STG;
    float* sNum = sm + OFF_NUM;
    float* sSq  = sm + OFF_SQ;
    float* sFsn = sm + OFF_FSN;

    const int n = blockIdx.x, q = blockIdx.y, b = blockIdx.z;
    const int tx = threadIdx.x, ty = threadIdx.y;
    const int tid = ty * 16 + tx;
    const int lane = tid & 31, wid = tid >> 5;

    const float* FQ = FQg + (size_t)(b * Q_ + q) * T_ * C_;
    const float* FS = FSg + (size_t)(b * N_ + n) * T_ * C_;
    const float4* FQ4 = reinterpret_cast<const float4*>(FQ);
    const float4* FS4 = reinterpret_cast<const float4*>(FS);

    // init accumulators
    for (int i = tid; i < T_; i += 256) { sNum[i] = 0.f; sSq[i] = 0.f; }

    // ||fs[t,:]||^2 per token
    for (int t = wid; t < T_; t += 8) {
        float s = 0.f;
        const float* row = FS + t * C_;
        for (int c = lane; c < C_; c += 32) { float v = row[c]; s = fmaf(v, v, s); }
        #pragma unroll
        for (int o = 16; o > 0; o >>= 1) s += __shfl_xor_sync(0xffffffffu, s, o);
        if (lane == 0) sFsn[t] = s;
    }
    __syncthreads();

    for (int ch = 0; ch < NCH; ++ch) {
        // ---- stage FQ chunk columns: sFQ[t][c1l], zero-padded rows ----
        for (int idx = tid; idx < TPQ * 16; idx += 256) {
            int t = idx >> 4, c4 = idx & 15;
            float4 v = make_float4(0.f, 0.f, 0.f, 0.f);
            if (t < T_) v = FQ4[t * 96 + ch * 16 + c4];
            reinterpret_cast<float4*>(sFQ)[t * 16 + c4] = v;
        }
        __syncthreads();

        // ---- GEMM1: attn[c1][c2] = sum_t FQ[t][c1]*FS[t][c2], K over t ----
        // thread (tx,ty): c1 = tx + 16*i (i<4), c2 = p*128 + ty*8 + j (j<8, packed pairs)
        for (int p = 0; p < 3; ++p) {
            unsigned long long acc[4][4];
            #pragma unroll
            for (int i = 0; i < 4; ++i)
                #pragma unroll
                for (int j = 0; j < 4; ++j) acc[i][j] = 0ull;

            for (int kk = 0; kk < T_; kk += 32) {
                // stage FS tile [32][128] (stride LDB), zero-fill t>=196
                for (int idx = tid; idx < 1024; idx += 256) {
                    int r = idx >> 5, c4 = idx & 31;
                    int t = kk + r;
                    float4 v = make_float4(0.f, 0.f, 0.f, 0.f);
                    if (t < T_) v = FS4[t * 96 + p * 32 + c4];
                    *reinterpret_cast<float4*>(&sStg[r * LDB + c4 * 4]) = v;
                }
                __syncthreads();
                #pragma unroll
                for (int k = 0; k < 32; ++k) {
                    float a_[4];
                    #pragma unroll
                    for (int i = 0; i < 4; ++i) a_[i] = sFQ[(kk + k) * 64 + tx + 16 * i];
                    const unsigned long long* bp =
                        reinterpret_cast<const unsigned long long*>(&sStg[k * LDB + ty * 8]);
                    unsigned long long bv[4];
                    #pragma unroll
                    for (int j = 0; j < 4; ++j) bv[j] = bp[j];
                    #pragma unroll
                    for (int i = 0; i < 4; ++i) {
                        unsigned long long av = pk2(a_[i], a_[i]);
                        #pragma unroll
                        for (int j = 0; j < 4; ++j) acc[i][j] = fma2(av, bv[j], acc[i][j]);
                    }
                }
                __syncthreads();
            }
            // store transposed+scaled: sAtt[c2][c1]; lane-contiguous in tx -> conflict-free
            #pragma unroll
            for (int i = 0; i < 4; ++i)
                #pragma unroll
                for (int j = 0; j < 4; ++j) {
                    float2 v = upk2(acc[i][j]);
                    int c2 = p * 128 + ty * 8 + 2 * j;
                    sAtt[(c2 + 0) * ALD + tx + 16 * i] = v.x * SCALE;
                    sAtt[(c2 + 1) * ALD + tx + 16 * i] = v.y * SCALE;
                }
        }
        __syncthreads();

        // ---- softmax over c2 (column of sAtt per c1), warp-per-row ----
        #pragma unroll
        for (int r = 0; r < 8; ++r) {
            int c1 = wid * 8 + r;
            float x[12];
            float mx = -1e30f;
            #pragma unroll
            for (int m = 0; m < 12; ++m) {
                x[m] = sAtt[(lane + 32 * m) * ALD + c1];
                mx = fmaxf(mx, x[m]);
            }
            #pragma unroll
            for (int o = 16; o > 0; o >>= 1) mx = fmaxf(mx, __shfl_xor_sync(0xffffffffu, mx, o));
            float s = 0.f;
            #pragma unroll
            for (int m = 0; m < 12; ++m) { x[m] = __expf(x[m] - mx); s += x[m]; }
            #pragma unroll
            for (int o = 16; o > 0; o >>= 1) s += __shfl_xor_sync(0xffffffffu, s, o);
            float inv = 1.f / s;
            #pragma unroll
            for (int m = 0; m < 12; ++m) sAtt[(lane + 32 * m) * ALD + c1] = x[m] * inv;
        }
        __syncthreads();

        // ---- GEMM2: fq_new[t][c1] = sum_c2 FQ[t][c2]*attn[c1][c2], K=384 ----
        // thread (tx,ty): t = ty + 16*i (i<13), c1 = tx*4 + j (j<4, packed pairs)
        unsigned long long acc2[13][2];
        #pragma unroll
        for (int i = 0; i < 13; ++i) { acc2[i][0] = 0ull; acc2[i][1] = 0ull; }

        for (int c2b = 0; c2b < C_; c2b += 32) {
            // stage FQ K-tile transposed: sStg[k][t], stride LDT (odd -> conflict-free)
            for (int idx = tid; idx < T_ * 8; idx += 256) {
                int t = idx >> 3, g = idx & 7;
                float4 v = FQ4[t * 96 + (c2b >> 2) + g];
                sStg[(g * 4 + 0) * LDT + t] = v.x;
                sStg[(g * 4 + 1) * LDT + t] = v.y;
                sStg[(g * 4 + 2) * LDT + t] = v.z;
                sStg[(g * 4 + 3) * LDT + t] = v.w;
            }
            __syncthreads();
            #pragma unroll
            for (int k = 0; k < 32; ++k) {
                const unsigned long long* bp =
                    reinterpret_cast<const unsigned long long*>(&sAtt[(c2b + k) * ALD + tx * 4]);
                unsigned long long bv0 = bp[0], bv1 = bp[1];
                #pragma unroll
                for (int i = 0; i < 13; ++i) {
                    int t = ty + 16 * i;
                    float a = (t < T_) ? sStg[k * LDT + t] : 0.f;
                    unsigned long long av = pk2(a, a);
                    acc2[i][0] = fma2(av, bv0, acc2[i][0]);
                    acc2[i][1] = fma2(av, bv1, acc2[i][1]);
                }
            }
            __syncthreads();
        }

        // ---- fused cosine epilogue: accumulate num[t], sq[t] ----
        #pragma unroll
        for (int i = 0; i < 13; ++i) {
            int t = ty + 16 * i;
            if (t < T_) {
                float2 p0 = upk2(acc2[i][0]);
                float2 p1 = upk2(acc2[i][1]);
                float4 fv = FS4[t * 96 + ch * 16 + tx];
                float nl = p0.x * fv.x + p0.y * fv.y + p1.x * fv.z + p1.y * fv.w;
                float sl = p0.x * p0.x + p0.y * p0.y + p1.x * p1.x + p1.y * p1.y;
                #pragma unroll
                for (int o = 1; o < 16; o <<= 1) {
                    nl += __shfl_xor_sync(0xffffffffu, nl, o);
                    sl += __shfl_xor_sync(0xffffffffu, sl, o);
                }
                if (tx == 0) { sNum[t] += nl; sSq[t] += sl; }
            }
        }
        __syncthreads();
    }

    // ---- top-1 over t, mean over n via atomicAdd ----
    if (wid == 0) {
        float best = -1e30f;
        for (int t = lane; t < T_; t += 32) {
            float den = fmaxf(sqrtf(sSq[t] * sFsn[t]), 1e-8f);
            best = fmaxf(best, sNum[t] / den);
        }
        #pragma unroll
        for (int o = 16; o > 0; o >>= 1) best = fmaxf(best, __shfl_xor_sync(0xffffffffu, best, o));
        if (lane == 0) atomicAdd(&out[b * Q_ + q], best * (1.0f / N_));
    }
}

// prototype-cosine branch: cls[b,q,n] = 10 * <xq_hat, xs_hat>
__global__ void tok_cls_kernel(const float* __restrict__ XQ,
                               const float* __restrict__ XS,
                               float* __restrict__ out)
{
    int w = (blockIdx.x * blockDim.x + threadIdx.x) >> 5;
    int lane = threadIdx.x & 31;
    if (w >= B_ * Q_ * N_) return;
    int n = w % N_;
    int bq = w / N_;
    int q = bq % Q_;
    int b = bq / Q_;
    const float* xq = XQ + (size_t)(b * Q_ + q) * D_;
    const float* xs = XS + (size_t)(b * N_ + n) * D_;
    float dot = 0.f, nq = 0.f, ns = 0.f;
    for (int d = lane; d < D_; d += 32) {
        float a = xq[d], c = xs[d];
        dot = fmaf(a, c, dot);
        nq  = fmaf(a, a, nq);
        ns  = fmaf(c, c, ns);
    }
    #pragma unroll
    for (int o = 16; o > 0; o >>= 1) {
        dot += __shfl_xor_sync(0xffffffffu, dot, o);
        nq  += __shfl_xor_sync(0xffffffffu, nq, o);
        ns  += __shfl_xor_sync(0xffffffffu, ns, o);
    }
    if (lane == 0) {
        float denom = fmaxf(sqrtf(nq), 1e-12f) * fmaxf(sqrtf(ns), 1e-12f);
        out[B_ * Q_ + w] = 10.0f * dot / denom;
    }
}

__global__ void tok_init_kernel(float* __restrict__ out)
{
    int i = blockIdx.x * blockDim.x + threadIdx.x;
    if (i < B_ * Q_) out[i] = 0.f;
}

extern "C" void kernel_launch(void* const* d_in, const int* in_sizes, int n_in,
                              void* d_out, int out_size)
{
    const float* fq = (const float*)d_in[0];  // feat_query (2,75,196,384)
    const float* fs = (const float*)d_in[1];  // feat_shot  (2,5,1,196,384)
    const float* xq = (const float*)d_in[2];  // x_query    (2,75,384)
    const float* xs = (const float*)d_in[3];  // x_shot     (2,5,1,384)
    float* out = (float*)d_out;               // [150 logits | 750 cls_logits]

    cudaFuncSetAttribute(tok_main_kernel,
                         cudaFuncAttributeMaxDynamicSharedMemorySize, SMEM_BYTES);

    tok_init_kernel<<<1, 256>>>(out);
    tok_cls_kernel<<<(B_ * Q_ * N_ * 32 + 255) / 256, 256>>>(xq, xs, out);
    dim3 grid(N_, Q_, B_), blk(16, 16);
    tok_main_kernel<<<grid, blk, SMEM_BYTES>>>(fq, fs, out);
}

// round 3
// speedup vs baseline: 1.4651x; 1.1687x over previous
#include <cuda_runtime.h>
#include <math.h>

namespace {
constexpr int B_ = 2, Q_ = 75, N_ = 5, T_ = 196, C_ = 384, D_ = 384;
constexpr int CHUNK = 64;               // c1 chunk
constexpr int NCH = C_ / CHUNK;         // 6
constexpr int KP = 224;                 // padded K for GEMM1 (= padded t)
constexpr int ALD = 68;                 // attn row stride [c2][c1], 16B-aligned rows
constexpr int LDF = 388;                // GEMM1 FS staging row stride (floats)
constexpr int LDD = 450;                // GEMM2 dup-FQ^T staging row stride (floats, even)
constexpr float SCALE = 1.0f / 14.0f;

// smem layout (floats)
constexpr int OFF_ATT = 0;                      // [384][ALD]
constexpr int OFF_FQ  = OFF_ATT + C_ * ALD;     // [KP][64]
constexpr int OFF_STG = OFF_FQ + KP * CHUNK;    // max(32*LDF, 32*LDD) = 32*LDD
constexpr int OFF_RED = OFF_STG + 32 * LDD;     // [64][17]
constexpr int OFF_NUM = OFF_RED + 64 * 17;
constexpr int OFF_SQ  = OFF_NUM + T_;
constexpr int OFF_FSN = OFF_SQ + T_;
constexpr int SMEM_FLOATS = OFF_FSN + T_;
constexpr int SMEM_BYTES = SMEM_FLOATS * 4;     // 226,096 B
}

typedef unsigned long long ull;

__device__ __forceinline__ ull pk2(float lo, float hi) {
    ull r; asm("mov.b64 %0, {%1, %2};" : "=l"(r) : "f"(lo), "f"(hi)); return r;
}
__device__ __forceinline__ float2 upk2(ull v) {
    float2 r; asm("mov.b64 {%0, %1}, %2;" : "=f"(r.x), "=f"(r.y) : "l"(v)); return r;
}
__device__ __forceinline__ ull fma2(ull a, ull b, ull c) {
    ull d; asm("fma.rn.f32x2 %0, %1, %2, %3;" : "=l"(d) : "l"(a), "l"(b), "l"(c)); return d;
}

// One CTA per (b,q,n). 256 threads.
__global__ void __launch_bounds__(256, 1)
tok_main_kernel(const float* __restrict__ FQg,
                const float* __restrict__ FSg,
                float* __restrict__ out)
{
    extern __shared__ float sm[];
    float* sAtt = sm + OFF_ATT;
    float* sFQ  = sm + OFF_FQ;
    float* sStg = sm + OFF_STG;   // FS tile (GEMM1) / dup FQ^T tile (GEMM2)
    float* sRed = sm + OFF_RED;
    float* sNum = sm + OFF_NUM;
    float* sSq  = sm + OFF_SQ;
    float* sFsn = sm + OFF_FSN;

    const int n = blockIdx.x, q = blockIdx.y, b = blockIdx.z;
    const int tid  = threadIdx.x;
    const int tx = tid & 15, ty = tid >> 4;   // GEMM1 / softmax layout
    const int cx = tid & 7,  wy = tid >> 3;   // GEMM2 / epilogue layout
    const int lane = tid & 31, wid = tid >> 5;

    const float* FQ = FQg + (size_t)(b * Q_ + q) * T_ * C_;
    const float* FS = FSg + (size_t)(b * N_ + n) * T_ * C_;
    const float4* FQ4 = reinterpret_cast<const float4*>(FQ);
    const float4* FS4 = reinterpret_cast<const float4*>(FS);

    for (int i = tid; i < T_; i += 256) { sNum[i] = 0.f; sSq[i] = 0.f; }

    // ||fs[t,:]||^2 per token
    for (int t = wid; t < T_; t += 8) {
        float s = 0.f;
        const float* row = FS + t * C_;
        for (int c = lane; c < C_; c += 32) { float v = row[c]; s = fmaf(v, v, s); }
        #pragma unroll
        for (int o = 16; o > 0; o >>= 1) s += __shfl_xor_sync(0xffffffffu, s, o);
        if (lane == 0) sFsn[t] = s;
    }
    __syncthreads();

    for (int ch = 0; ch < NCH; ++ch) {
        // ---------- stage FQ chunk columns: sFQ[t][64], zero-padded t>=196 ----------
        for (int idx = tid; idx < KP * 16; idx += 256) {
            int t = idx >> 4, c4 = idx & 15;
            float4 v = make_float4(0.f, 0.f, 0.f, 0.f);
            if (t < T_) v = FQ4[t * 96 + ch * 16 + c4];
            *reinterpret_cast<float4*>(&sFQ[t * 64 + c4 * 4]) = v;
        }
        __syncthreads();

        // ---------- GEMM1: raw attn logits, thread tile 4 c1 x 12 c2-pairs ----------
        ull acc1[4][12];
        #pragma unroll
        for (int i = 0; i < 4; ++i)
            #pragma unroll
            for (int j = 0; j < 12; ++j) acc1[i][j] = 0ull;

        for (int kk = 0; kk < KP; kk += 32) {
            for (int idx = tid; idx < 32 * 96; idx += 256) {
                int r = idx / 96, c4 = idx % 96;
                int t = kk + r;
                float4 v = make_float4(0.f, 0.f, 0.f, 0.f);
                if (t < T_) v = FS4[t * 96 + c4];
                *reinterpret_cast<float4*>(&sStg[r * LDF + c4 * 4]) = v;
            }
            __syncthreads();
            #pragma unroll
            for (int k0 = 0; k0 < 32; ++k0) {
                float4 a4 = *reinterpret_cast<const float4*>(&sFQ[(kk + k0) * 64 + tx * 4]);
                ull a_[4];
                a_[0] = pk2(a4.x, a4.x); a_[1] = pk2(a4.y, a4.y);
                a_[2] = pk2(a4.z, a4.z); a_[3] = pk2(a4.w, a4.w);
                const ulonglong2* bp =
                    reinterpret_cast<const ulonglong2*>(&sStg[k0 * LDF + ty * 24]);
                ull bv[12];
                #pragma unroll
                for (int j = 0; j < 6; ++j) { ulonglong2 u = bp[j]; bv[2*j] = u.x; bv[2*j+1] = u.y; }
                #pragma unroll
                for (int i = 0; i < 4; ++i)
                    #pragma unroll
                    for (int j = 0; j < 12; ++j) acc1[i][j] = fma2(a_[i], bv[j], acc1[i][j]);
            }
            __syncthreads();
        }

        // ---------- softmax over c2, in registers ----------
        // thread owns c1 = tx*4+i, c2 = ty*24 + (0..23) (raw logits; scale folded here)
        float M[4], S[4];
        #pragma unroll
        for (int i = 0; i < 4; ++i) {
            float m = -1e30f;
            #pragma unroll
            for (int j = 0; j < 12; ++j) {
                float2 p = upk2(acc1[i][j]);
                m = fmaxf(m, fmaxf(p.x, p.y));
            }
            sRed[(tx * 4 + i) * 17 + ty] = m * SCALE;
        }
        __syncthreads();
        #pragma unroll
        for (int i = 0; i < 4; ++i) {
            float m = -1e30f;
            #pragma unroll
            for (int u = 0; u < 16; ++u) m = fmaxf(m, sRed[(tx * 4 + i) * 17 + u]);
            M[i] = m;
        }
        __syncthreads();
        #pragma unroll
        for (int i = 0; i < 4; ++i) {
            float s = 0.f;
            #pragma unroll
            for (int j = 0; j < 12; ++j) {
                float2 p = upk2(acc1[i][j]);
                s += __expf(fmaf(p.x, SCALE, -M[i])) + __expf(fmaf(p.y, SCALE, -M[i]));
            }
            sRed[(tx * 4 + i) * 17 + ty] = s;
        }
        __syncthreads();
        #pragma unroll
        for (int i = 0; i < 4; ++i) {
            float s = 0.f;
            #pragma unroll
            for (int u = 0; u < 16; ++u) s += sRed[(tx * 4 + i) * 17 + u];
            S[i] = 1.f / s;
        }
        // normalized store (transposed scatter): sAtt[c2][c1]
        #pragma unroll
        for (int i = 0; i < 4; ++i)
            #pragma unroll
            for (int j = 0; j < 12; ++j) {
                float2 p = upk2(acc1[i][j]);
                int c2 = ty * 24 + 2 * j;
                sAtt[(c2 + 0) * ALD + tx * 4 + i] = __expf(fmaf(p.x, SCALE, -M[i])) * S[i];
                sAtt[(c2 + 1) * ALD + tx * 4 + i] = __expf(fmaf(p.y, SCALE, -M[i])) * S[i];
            }
        __syncthreads();

        // ---------- GEMM2: fq_new[t][c1] = sum_c2 FQ[t][c2]*attn[c2][c1] ----------
        // thread tile: t = wy+32i (i<7), c1-pairs cx*4+jj (jj<4 -> c1 = cx*8..+7)
        ull acc2[7][4];
        #pragma unroll
        for (int i = 0; i < 7; ++i)
            #pragma unroll
            for (int j = 0; j < 4; ++j) acc2[i][j] = 0ull;

        for (int c2b = 0; c2b < C_; c2b += 32) {
            // stage dup FQ^T: sStg[k][2t]=(v,v); k local, t<196 (t>=196 left stale, unused)
            for (int idx = tid; idx < T_ * 8; idx += 256) {
                int t = idx >> 3, g = idx & 7;
                float4 v = FQ4[t * 96 + (c2b >> 2) + g];
                sStg[(4 * g + 0) * LDD + 2 * t]     = v.x;
                sStg[(4 * g + 0) * LDD + 2 * t + 1] = v.x;
                sStg[(4 * g + 1) * LDD + 2 * t]     = v.y;
                sStg[(4 * g + 1) * LDD + 2 * t + 1] = v.y;
                sStg[(4 * g + 2) * LDD + 2 * t]     = v.z;
                sStg[(4 * g + 2) * LDD + 2 * t + 1] = v.z;
                sStg[(4 * g + 3) * LDD + 2 * t]     = v.w;
                sStg[(4 * g + 3) * LDD + 2 * t + 1] = v.w;
            }
            __syncthreads();
            #pragma unroll
            for (int k0 = 0; k0 < 32; ++k0) {
                const ulonglong2* bp =
                    reinterpret_cast<const ulonglong2*>(&sAtt[(c2b + k0) * ALD + cx * 8]);
                ulonglong2 b01 = bp[0], b23 = bp[1];
                ull bv[4] = { b01.x, b01.y, b23.x, b23.y };
                ull a_[7];
                #pragma unroll
                for (int i = 0; i < 7; ++i)
                    a_[i] = *reinterpret_cast<const ull*>(&sStg[k0 * LDD + 2 * (wy + 32 * i)]);
                #pragma unroll
                for (int i = 0; i < 7; ++i)
                    #pragma unroll
                    for (int j = 0; j < 4; ++j) acc2[i][j] = fma2(a_[i], bv[j], acc2[i][j]);
            }
            __syncthreads();
        }

        // ---------- fused cosine epilogue ----------
        #pragma unroll
        for (int i = 0; i < 7; ++i) {
            int t = wy + 32 * i;
            if (t < T_) {   // warp-uniform (warp spans 4 consecutive wy)
                float2 p0 = upk2(acc2[i][0]);
                float2 p1 = upk2(acc2[i][1]);
                float2 p2 = upk2(acc2[i][2]);
                float2 p3 = upk2(acc2[i][3]);
                float4 f0 = FS4[t * 96 + ch * 16 + cx * 2];
                float4 f1 = FS4[t * 96 + ch * 16 + cx * 2 + 1];
                float nl = p0.x * f0.x + p0.y * f0.y + p1.x * f0.z + p1.y * f0.w
                         + p2.x * f1.x + p2.y * f1.y + p3.x * f1.z + p3.y * f1.w;
                float sl = p0.x * p0.x + p0.y * p0.y + p1.x * p1.x + p1.y * p1.y
                         + p2.x * p2.x + p2.y * p2.y + p3.x * p3.x + p3.y * p3.y;
                #pragma unroll
                for (int o = 1; o < 8; o <<= 1) {
                    nl += __shfl_xor_sync(0xffffffffu, nl, o);
                    sl += __shfl_xor_sync(0xffffffffu, sl, o);
                }
                if (cx == 0) { sNum[t] += nl; sSq[t] += sl; }
            }
        }
        __syncthreads();
    }

    // ---------- top-1 over t, mean over n ----------
    if (wid == 0) {
        float best = -1e30f;
        for (int t = lane; t < T_; t += 32) {
            float den = fmaxf(sqrtf(sSq[t] * sFsn[t]), 1e-8f);
            best = fmaxf(best, sNum[t] / den);
        }
        #pragma unroll
        for (int o = 16; o > 0; o >>= 1) best = fmaxf(best, __shfl_xor_sync(0xffffffffu, best, o));
        if (lane == 0) atomicAdd(&out[b * Q_ + q], best * (1.0f / N_));
    }
}

// prototype-cosine branch
__global__ void tok_cls_kernel(const float* __restrict__ XQ,
                               const float* __restrict__ XS,
                               float* __restrict__ out)
{
    int w = (blockIdx.x * blockDim.x + threadIdx.x) >> 5;
    int lane = threadIdx.x & 31;
    if (w >= B_ * Q_ * N_) return;
    int n = w % N_;
    int bq = w / N_;
    int q = bq % Q_;
    int b = bq / Q_;
    const float* xq = XQ + (size_t)(b * Q_ + q) * D_;
    const float* xs = XS + (size_t)(b * N_ + n) * D_;
    float dot = 0.f, nq = 0.f, ns = 0.f;
    for (int d = lane; d < D_; d += 32) {
        float a = xq[d], c = xs[d];
        dot = fmaf(a, c, dot);
        nq  = fmaf(a, a, nq);
        ns  = fmaf(c, c, ns);
    }
    #pragma unroll
    for (int o = 16; o > 0; o >>= 1) {
        dot += __shfl_xor_sync(0xffffffffu, dot, o);
        nq  += __shfl_xor_sync(0xffffffffu, nq, o);
        ns  += __shfl_xor_sync(0xffffffffu, ns, o);
    }
    if (lane == 0) {
        float denom = fmaxf(sqrtf(nq), 1e-12f) * fmaxf(sqrtf(ns), 1e-12f);
        out[B_ * Q_ + w] = 10.0f * dot / denom;
    }
}

__global__ void tok_init_kernel(float* __restrict__ out)
{
    int i = blockIdx.x * blockDim.x + threadIdx.x;
    if (i < B_ * Q_) out[i] = 0.f;
}

extern "C" void kernel_launch(void* const* d_in, const int* in_sizes, int n_in,
                              void* d_out, int out_size)
{
    const float* fq = (const float*)d_in[0];
    const float* fs = (const float*)d_in[1];
    const float* xq = (const float*)d_in[2];
    const float* xs = (const float*)d_in[3];
    float* out = (float*)d_out;

    cudaFuncSetAttribute(tok_main_kernel,
                         cudaFuncAttributeMaxDynamicSharedMemorySize, SMEM_BYTES);

    tok_init_kernel<<<1, 256>>>(out);
    tok_cls_kernel<<<(B_ * Q_ * N_ * 32 + 255) / 256, 256>>>(xq, xs, out);
    dim3 grid(N_, Q_, B_);
    tok_main_kernel<<<grid, 256, SMEM_BYTES>>>(fq, fs, out);
}

// round 6
// speedup vs baseline: 1.7111x; 1.1679x over previous
#include <cuda_runtime.h>
#include <math.h>

namespace {
constexpr int B_ = 2, Q_ = 75, N_ = 5, T_ = 196, C_ = 384, D_ = 384;
constexpr int CHUNK = 64;               // c1 chunk
constexpr int NCH = C_ / CHUNK;         // 6
constexpr int ALD = 68;                 // attn row stride [c2][c1local], 16B-aligned rows
constexpr int LDF = 388;                // GEMM1 FS staging row stride (floats)
constexpr int LDT = 211;                // GEMM2 FQ^T staging row stride (odd)
constexpr float SCALE = 1.0f / 14.0f;

// smem layout (floats)
constexpr int OFF_ATT = 0;                      // [384][ALD]
constexpr int OFF_FQ  = OFF_ATT + C_ * ALD;     // [196][64]
constexpr int OFF_STG = OFF_FQ + T_ * CHUNK;    // 32*LDF (>= 32*LDT+pad)
constexpr int STG_SZ  = 32 * LDF;               // 12416
constexpr int OFF_RED = OFF_STG + STG_SZ;       // [64][17]
constexpr int OFF_NUM = OFF_RED + 64 * 17;
constexpr int OFF_SQ  = OFF_NUM + T_;
constexpr int OFF_FSN = OFF_SQ + T_;
constexpr int SMEM_FLOATS = OFF_FSN + T_;
constexpr int SMEM_BYTES = SMEM_FLOATS * 4;     // ~211 KB
}

typedef unsigned long long ull;

__device__ __forceinline__ ull pk2(float lo, float hi) {
    ull r; asm("mov.b64 %0, {%1, %2};" : "=l"(r) : "f"(lo), "f"(hi)); return r;
}
__device__ __forceinline__ float2 upk2(ull v) {
    float2 r; asm("mov.b64 {%0, %1}, %2;" : "=f"(r.x), "=f"(r.y) : "l"(v)); return r;
}
__device__ __forceinline__ ull fma2(ull a, ull b, ull c) {
    ull d; asm("fma.rn.f32x2 %0, %1, %2, %3;" : "=l"(d) : "l"(a), "l"(b), "l"(c)); return d;
}

// One CTA per (b,q,n). 256 threads.
__global__ void __launch_bounds__(256, 1)
tok_main_kernel(const float* __restrict__ FQg,
                const float* __restrict__ FSg,
                float* __restrict__ out)
{
    extern __shared__ float sm[];
    float* sAtt = sm + OFF_ATT;
    float* sFQ  = sm + OFF_FQ;
    float* sStg = sm + OFF_STG;
    float* sRed = sm + OFF_RED;
    float* sNum = sm + OFF_NUM;
    float* sSq  = sm + OFF_SQ;
    float* sFsn = sm + OFF_FSN;

    const int n = blockIdx.x, q = blockIdx.y, b = blockIdx.z;
    const int tid = threadIdx.x;
    const int tx = tid & 15, ty = tid >> 4;   // GEMM1 / softmax layout
    const int cx = tid & 7,  wy = tid >> 3;   // GEMM2 / epilogue layout
    const int lane = tid & 31, wid = tid >> 5;

    const float* FQ = FQg + (size_t)(b * Q_ + q) * T_ * C_;
    const float* FS = FSg + (size_t)(b * N_ + n) * T_ * C_;
    const float4* FQ4 = reinterpret_cast<const float4*>(FQ);
    const float4* FS4 = reinterpret_cast<const float4*>(FS);

    for (int i = tid; i < T_; i += 256) { sNum[i] = 0.f; sSq[i] = 0.f; }

    // ||fs[t,:]||^2 per token
    for (int t = wid; t < T_; t += 8) {
        float s = 0.f;
        const float* row = FS + t * C_;
        for (int c = lane; c < C_; c += 32) { float v = row[c]; s = fmaf(v, v, s); }
        #pragma unroll
        for (int o = 16; o > 0; o >>= 1) s += __shfl_xor_sync(0xffffffffu, s, o);
        if (lane == 0) sFsn[t] = s;
    }
    __syncthreads();

    for (int ch = 0; ch < NCH; ++ch) {
        // ---------- stage FQ chunk columns: sFQ[t][64], t < 196 ----------
        for (int idx = tid; idx < T_ * 16; idx += 256) {
            int t = idx >> 4, c4 = idx & 15;
            float4 v = FQ4[t * 96 + ch * 16 + c4];
            *reinterpret_cast<float4*>(&sFQ[t * 64 + c4 * 4]) = v;
        }
        __syncthreads();

        // ---------- GEMM1: attn logits, thread tile 4 c1 x 12 c2-pairs ----------
        ull acc1[4][12];
        #pragma unroll
        for (int i = 0; i < 4; ++i)
            #pragma unroll
            for (int j = 0; j < 12; ++j) acc1[i][j] = 0ull;

        // 6 full 32-row K tiles (k = 0..191)
        for (int kk = 0; kk < 192; kk += 32) {
            for (int idx = tid; idx < 32 * 96; idx += 256) {
                int r = idx / 96, c4 = idx % 96;
                float4 v = FS4[(kk + r) * 96 + c4];
                *reinterpret_cast<float4*>(&sStg[r * LDF + c4 * 4]) = v;
            }
            __syncthreads();
            #pragma unroll
            for (int k0 = 0; k0 < 32; ++k0) {
                float4 a4 = *reinterpret_cast<const float4*>(&sFQ[(kk + k0) * 64 + tx * 4]);
                ull a_[4];
                a_[0] = pk2(a4.x, a4.x); a_[1] = pk2(a4.y, a4.y);
                a_[2] = pk2(a4.z, a4.z); a_[3] = pk2(a4.w, a4.w);
                const ulonglong2* bp =
                    reinterpret_cast<const ulonglong2*>(&sStg[k0 * LDF + ty * 24]);
                ull bv[12];
                #pragma unroll
                for (int j = 0; j < 6; ++j) { ulonglong2 u = bp[j]; bv[2*j] = u.x; bv[2*j+1] = u.y; }
                #pragma unroll
                for (int i = 0; i < 4; ++i)
                    #pragma unroll
                    for (int j = 0; j < 12; ++j) acc1[i][j] = fma2(a_[i], bv[j], acc1[i][j]);
            }
            __syncthreads();
        }
        // tail: k = 192..195
        for (int idx = tid; idx < 4 * 96; idx += 256) {
            int r = idx / 96, c4 = idx % 96;
            float4 v = FS4[(192 + r) * 96 + c4];
            *reinterpret_cast<float4*>(&sStg[r * LDF + c4 * 4]) = v;
        }
        __syncthreads();
        #pragma unroll
        for (int k0 = 0; k0 < 4; ++k0) {
            float4 a4 = *reinterpret_cast<const float4*>(&sFQ[(192 + k0) * 64 + tx * 4]);
            ull a_[4];
            a_[0] = pk2(a4.x, a4.x); a_[1] = pk2(a4.y, a4.y);
            a_[2] = pk2(a4.z, a4.z); a_[3] = pk2(a4.w, a4.w);
            const ulonglong2* bp =
                reinterpret_cast<const ulonglong2*>(&sStg[k0 * LDF + ty * 24]);
            ull bv[12];
            #pragma unroll
            for (int j = 0; j < 6; ++j) { ulonglong2 u = bp[j]; bv[2*j] = u.x; bv[2*j+1] = u.y; }
            #pragma unroll
            for (int i = 0; i < 4; ++i)
                #pragma unroll
                for (int j = 0; j < 12; ++j) acc1[i][j] = fma2(a_[i], bv[j], acc1[i][j]);
        }
        __syncthreads();

        // ---------- softmax over c2, in registers ----------
        // thread owns c1 = tx*4+i, c2 = ty*24 + 2j{,+1}
        float M[4], S[4];
        #pragma unroll
        for (int i = 0; i < 4; ++i) {
            float m = -1e30f;
            #pragma unroll
            for (int j = 0; j < 12; ++j) {
                float2 p = upk2(acc1[i][j]);
                m = fmaxf(m, fmaxf(p.x, p.y));
            }
            sRed[(tx * 4 + i) * 17 + ty] = m * SCALE;
        }
        __syncthreads();
        #pragma unroll
        for (int i = 0; i < 4; ++i) {
            float m = -1e30f;
            #pragma unroll
            for (int u = 0; u < 16; ++u) m = fmaxf(m, sRed[(tx * 4 + i) * 17 + u]);
            M[i] = m;
        }
        __syncthreads();
        #pragma unroll
        for (int i = 0; i < 4; ++i) {
            float s = 0.f;
            #pragma unroll
            for (int j = 0; j < 12; ++j) {
                float2 p = upk2(acc1[i][j]);
                float e0 = __expf(fmaf(p.x, SCALE, -M[i]));
                float e1 = __expf(fmaf(p.y, SCALE, -M[i]));
                s += e0 + e1;
                acc1[i][j] = pk2(e0, e1);   // cache exp values
            }
            sRed[(tx * 4 + i) * 17 + ty] = s;
        }
        __syncthreads();
        #pragma unroll
        for (int i = 0; i < 4; ++i) {
            float s = 0.f;
            #pragma unroll
            for (int u = 0; u < 16; ++u) s += sRed[(tx * 4 + i) * 17 + u];
            S[i] = 1.f / s;
        }
        // normalized store (transposed scatter): sAtt[c2][c1]
        #pragma unroll
        for (int i = 0; i < 4; ++i)
            #pragma unroll
            for (int j = 0; j < 12; ++j) {
                float2 p = upk2(acc1[i][j]);
                int c2 = ty * 24 + 2 * j;
                sAtt[(c2 + 0) * ALD + tx * 4 + i] = p.x * S[i];
                sAtt[(c2 + 1) * ALD + tx * 4 + i] = p.y * S[i];
            }
        __syncthreads();

        // ---------- GEMM2: fq_new[t][c1] = sum_c2 FQ[t][c2]*attn[c2][c1] ----------
        // thread: t = wy + 32i (i<7); c1 pairs {2cx,2cx+1} and {16+2cx,16+2cx+1}
        ull acc2[7][4];
        #pragma unroll
        for (int i = 0; i < 7; ++i)
            #pragma unroll
            for (int j = 0; j < 4; ++j) acc2[i][j] = 0ull;

        for (int c2b = 0; c2b < C_; c2b += 32) {
            // stage FQ K-tile transposed: sStg[c2local][t]
            for (int idx = tid; idx < T_ * 8; idx += 256) {
                int t = idx >> 3, g = idx & 7;
                float4 v = FQ4[t * 96 + (c2b >> 2) + g];
                sStg[(4 * g + 0) * LDT + t] = v.x;
                sStg[(4 * g + 1) * LDT + t] = v.y;
                sStg[(4 * g + 2) * LDT + t] = v.z;
                sStg[(4 * g + 3) * LDT + t] = v.w;
            }
            __syncthreads();
            #pragma unroll
            for (int k0 = 0; k0 < 32; ++k0) {
                const float* arow = &sAtt[(c2b + k0) * ALD];
                const ulonglong2 b01 = *reinterpret_cast<const ulonglong2*>(&arow[cx * 4]);
                const ulonglong2 b23 = *reinterpret_cast<const ulonglong2*>(&arow[32 + cx * 4]);
                ull bv[4] = { b01.x, b01.y, b23.x, b23.y };
                const float* srow = &sStg[k0 * LDT];
                #pragma unroll
                for (int i = 0; i < 7; ++i) {
                    float a = srow[wy + 32 * i];
                    ull av = pk2(a, a);
                    #pragma unroll
                    for (int j = 0; j < 4; ++j) acc2[i][j] = fma2(av, bv[j], acc2[i][j]);
                }
            }
            __syncthreads();
        }

        // ---------- fused cosine epilogue ----------
        #pragma unroll
        for (int i = 0; i < 7; ++i) {
            int t = wy + 32 * i;
            if (t < T_) {   // warp-uniform (warp = 4 consecutive wy)
                float2 p0 = upk2(acc2[i][0]);
                float2 p1 = upk2(acc2[i][1]);
                float2 p2 = upk2(acc2[i][2]);
                float2 p3 = upk2(acc2[i][3]);
                float4 f0 = FS4[t * 96 + ch * 16 + cx];       // c1 = cx*4..+3
                float4 f1 = FS4[t * 96 + ch * 16 + 8 + cx];   // c1 = 32+cx*4..+3
                float nl = p0.x * f0.x + p0.y * f0.y + p1.x * f0.z + p1.y * f0.w
                         + p2.x * f1.x + p2.y * f1.y + p3.x * f1.z + p3.y * f1.w;
                float sl = p0.x * p0.x + p0.y * p0.y + p1.x * p1.x + p1.y * p1.y
                         + p2.x * p2.x + p2.y * p2.y + p3.x * p3.x + p3.y * p3.y;
                #pragma unroll
                for (int o = 1; o < 8; o <<= 1) {
                    nl += __shfl_xor_sync(0xffffffffu, nl, o);
                    sl += __shfl_xor_sync(0xffffffffu, sl, o);
                }
                if (cx == 0) { sNum[t] += nl; sSq[t] += sl; }
            }
        }
        __syncthreads();
    }

    // ---------- top-1 over t, mean over n ----------
    if (wid == 0) {
        float best = -1e30f;
        for (int t = lane; t < T_; t += 32) {
            float den = fmaxf(sqrtf(sSq[t] * sFsn[t]), 1e-8f);
            best = fmaxf(best, sNum[t] / den);
        }
        #pragma unroll
        for (int o = 16; o > 0; o >>= 1) best = fmaxf(best, __shfl_xor_sync(0xffffffffu, best, o));
        if (lane == 0) atomicAdd(&out[b * Q_ + q], best * (1.0f / N_));
    }
}

// prototype-cosine branch + output init (merged so the replay is 2 launches)
__global__ void tok_cls_init_kernel(const float* __restrict__ XQ,
                                    const float* __restrict__ XS,
                                    float* __restrict__ out)
{
    int gtid = blockIdx.x * blockDim.x + threadIdx.x;
    if (gtid < B_ * Q_) out[gtid] = 0.f;
    int w = gtid >> 5;
    int lane = gtid & 31;
    if (w >= B_ * Q_ * N_) return;
    int n = w % N_;
    int bq = w / N_;
    int q = bq % Q_;
    int b = bq / Q_;
    const float* xq = XQ + (size_t)(b * Q_ + q) * D_;
    const float* xs = XS + (size_t)(b * N_ + n) * D_;
    float dot = 0.f, nq = 0.f, ns = 0.f;
    for (int d = lane; d < D_; d += 32) {
        float a = xq[d], c = xs[d];
        dot = fmaf(a, c, dot);
        nq  = fmaf(a, a, nq);
        ns  = fmaf(c, c, ns);
    }
    #pragma unroll
    for (int o = 16; o > 0; o >>= 1) {
        dot += __shfl_xor_sync(0xffffffffu, dot, o);
        nq  += __shfl_xor_sync(0xffffffffu, nq, o);
        ns  += __shfl_xor_sync(0xffffffffu, ns, o);
    }
    if (lane == 0) {
        float denom = fmaxf(sqrtf(nq), 1e-12f) * fmaxf(sqrtf(ns), 1e-12f);
        out[B_ * Q_ + w] = 10.0f * dot / denom;
    }
}

extern "C" void kernel_launch(void* const* d_in, const int* in_sizes, int n_in,
                              void* d_out, int out_size)
{
    const float* fq = (const float*)d_in[0];
    const float* fs = (const float*)d_in[1];
    const float* xq = (const float*)d_in[2];
    const float* xs = (const float*)d_in[3];
    float* out = (float*)d_out;

    cudaFuncSetAttribute(tok_main_kernel,
                         cudaFuncAttributeMaxDynamicSharedMemorySize, SMEM_BYTES);

    tok_cls_init_kernel<<<(B_ * Q_ * N_ * 32 + 255) / 256, 256>>>(xq, xs, out);
    dim3 grid(N_, Q_, B_);
    tok_main_kernel<<<grid, 256, SMEM_BYTES>>>(fq, fs, out);
}

// round 7
// speedup vs baseline: 1.8746x; 1.0956x over previous
#include <cuda_runtime.h>
#include <math.h>

namespace {
constexpr int B_ = 2, Q_ = 75, N_ = 5, T_ = 196, C_ = 384, D_ = 384;
constexpr int CHUNK = 64;               // c1 chunk
constexpr int NCH = C_ / CHUNK;         // 6
constexpr int ALD = 68;                 // attn row stride [c2][c1local], 16B-aligned rows
constexpr int LDT = 211;                // GEMM2 FQ^T staging row stride (odd)
constexpr float SCALE = 1.0f / 14.0f;

// smem layout (floats)
constexpr int OFF_ATT = 0;                      // [384][ALD]
constexpr int OFF_FQ  = OFF_ATT + C_ * ALD;     // [196][64]
constexpr int OFF_STG = OFF_FQ + T_ * CHUNK;    // 64 x LDT (GEMM2 k-tile)
constexpr int STG_SZ  = 64 * LDT;               // 13504
constexpr int OFF_RED = OFF_STG + STG_SZ;       // [64][17]
constexpr int OFF_NUM = OFF_RED + 64 * 17;
constexpr int OFF_SQ  = OFF_NUM + T_;
constexpr int OFF_FSN = OFF_SQ + T_;
constexpr int SMEM_FLOATS = OFF_FSN + T_;
constexpr int SMEM_BYTES = SMEM_FLOATS * 4;     // ~216 KB
}

typedef unsigned long long ull;

__device__ __forceinline__ ull pk2(float lo, float hi) {
    ull r; asm("mov.b64 %0, {%1, %2};" : "=l"(r) : "f"(lo), "f"(hi)); return r;
}
__device__ __forceinline__ float2 upk2(ull v) {
    float2 r; asm("mov.b64 {%0, %1}, %2;" : "=f"(r.x), "=f"(r.y) : "l"(v)); return r;
}
__device__ __forceinline__ ull fma2(ull a, ull b, ull c) {
    ull d; asm("fma.rn.f32x2 %0, %1, %2, %3;" : "=l"(d) : "l"(a), "l"(b), "l"(c)); return d;
}

// One CTA per (b,q,n). 256 threads.
__global__ void __launch_bounds__(256, 1)
tok_main_kernel(const float* __restrict__ FQg,
                const float* __restrict__ FSg,
                float* __restrict__ out)
{
    extern __shared__ float sm[];
    float* sAtt = sm + OFF_ATT;
    float* sFQ  = sm + OFF_FQ;
    float* sStg = sm + OFF_STG;
    float* sRed = sm + OFF_RED;
    float* sNum = sm + OFF_NUM;
    float* sSq  = sm + OFF_SQ;
    float* sFsn = sm + OFF_FSN;

    const int n = blockIdx.x, q = blockIdx.y, b = blockIdx.z;
    const int tid = threadIdx.x;
    const int tx = tid & 15, ty = tid >> 4;   // GEMM1 / softmax layout
    const int cx = tid & 7,  wy = tid >> 3;   // GEMM2 / epilogue layout
    const int lane = tid & 31, wid = tid >> 5;

    const float* FQ = FQg + (size_t)(b * Q_ + q) * T_ * C_;
    const float* FS = FSg + (size_t)(b * N_ + n) * T_ * C_;
    const float4* FQ4 = reinterpret_cast<const float4*>(FQ);
    const float4* FS4 = reinterpret_cast<const float4*>(FS);

    for (int i = tid; i < T_; i += 256) { sNum[i] = 0.f; sSq[i] = 0.f; }

    // ||fs[t,:]||^2 per token
    for (int t = wid; t < T_; t += 8) {
        float s = 0.f;
        const float* row = FS + t * C_;
        for (int c = lane; c < C_; c += 32) { float v = row[c]; s = fmaf(v, v, s); }
        #pragma unroll
        for (int o = 16; o > 0; o >>= 1) s += __shfl_xor_sync(0xffffffffu, s, o);
        if (lane == 0) sFsn[t] = s;
    }
    __syncthreads();

    for (int ch = 0; ch < NCH; ++ch) {
        // ---------- stage FQ chunk columns: sFQ[t][64], t < 196 ----------
        for (int idx = tid; idx < T_ * 16; idx += 256) {
            int t = idx >> 4, c4 = idx & 15;
            float4 v = FQ4[t * 96 + ch * 16 + c4];
            *reinterpret_cast<float4*>(&sFQ[t * 64 + c4 * 4]) = v;
        }
        __syncthreads();

        // ---------- GEMM1: attn logits; b read straight from global (L2) ----------
        // thread (tx,ty): c1 = tx*4+i (i<4), c2 = ty*24 + 2j{,+1} (j<12)
        ull acc1[4][12];
        #pragma unroll
        for (int i = 0; i < 4; ++i)
            #pragma unroll
            for (int j = 0; j < 12; ++j) acc1[i][j] = 0ull;

        {
            const ulonglong2* fsb = reinterpret_cast<const ulonglong2*>(FS) + ty * 6;
            #pragma unroll 4
            for (int k = 0; k < T_; ++k) {
                ulonglong2 b0 = fsb[k * 96 + 0];
                ulonglong2 b1 = fsb[k * 96 + 1];
                ulonglong2 b2 = fsb[k * 96 + 2];
                ulonglong2 b3 = fsb[k * 96 + 3];
                ulonglong2 b4 = fsb[k * 96 + 4];
                ulonglong2 b5 = fsb[k * 96 + 5];
                float4 a4 = *reinterpret_cast<const float4*>(&sFQ[k * 64 + tx * 4]);
                ull a_[4];
                a_[0] = pk2(a4.x, a4.x); a_[1] = pk2(a4.y, a4.y);
                a_[2] = pk2(a4.z, a4.z); a_[3] = pk2(a4.w, a4.w);
                #pragma unroll
                for (int i = 0; i < 4; ++i) {
                    acc1[i][0]  = fma2(a_[i], b0.x, acc1[i][0]);
                    acc1[i][1]  = fma2(a_[i], b0.y, acc1[i][1]);
                    acc1[i][2]  = fma2(a_[i], b1.x, acc1[i][2]);
                    acc1[i][3]  = fma2(a_[i], b1.y, acc1[i][3]);
                    acc1[i][4]  = fma2(a_[i], b2.x, acc1[i][4]);
                    acc1[i][5]  = fma2(a_[i], b2.y, acc1[i][5]);
                    acc1[i][6]  = fma2(a_[i], b3.x, acc1[i][6]);
                    acc1[i][7]  = fma2(a_[i], b3.y, acc1[i][7]);
                    acc1[i][8]  = fma2(a_[i], b4.x, acc1[i][8]);
                    acc1[i][9]  = fma2(a_[i], b4.y, acc1[i][9]);
                    acc1[i][10] = fma2(a_[i], b5.x, acc1[i][10]);
                    acc1[i][11] = fma2(a_[i], b5.y, acc1[i][11]);
                }
            }
        }

        // ---------- softmax over c2, in registers ----------
        float M[4], S[4];
        #pragma unroll
        for (int i = 0; i < 4; ++i) {
            float m = -1e30f;
            #pragma unroll
            for (int j = 0; j < 12; ++j) {
                float2 p = upk2(acc1[i][j]);
                m = fmaxf(m, fmaxf(p.x, p.y));
            }
            sRed[(tx * 4 + i) * 17 + ty] = m * SCALE;
        }
        __syncthreads();
        #pragma unroll
        for (int i = 0; i < 4; ++i) {
            float m = -1e30f;
            #pragma unroll
            for (int u = 0; u < 16; ++u) m = fmaxf(m, sRed[(tx * 4 + i) * 17 + u]);
            M[i] = m;
        }
        __syncthreads();
        #pragma unroll
        for (int i = 0; i < 4; ++i) {
            float s = 0.f;
            #pragma unroll
            for (int j = 0; j < 12; ++j) {
                float2 p = upk2(acc1[i][j]);
                float e0 = __expf(fmaf(p.x, SCALE, -M[i]));
                float e1 = __expf(fmaf(p.y, SCALE, -M[i]));
                s += e0 + e1;
                acc1[i][j] = pk2(e0, e1);   // cache exp values
            }
            sRed[(tx * 4 + i) * 17 + ty] = s;
        }
        __syncthreads();
        #pragma unroll
        for (int i = 0; i < 4; ++i) {
            float s = 0.f;
            #pragma unroll
            for (int u = 0; u < 16; ++u) s += sRed[(tx * 4 + i) * 17 + u];
            S[i] = 1.f / s;
        }
        // normalized store (transposed scatter): sAtt[c2][c1]
        #pragma unroll
        for (int i = 0; i < 4; ++i)
            #pragma unroll
            for (int j = 0; j < 12; ++j) {
                float2 p = upk2(acc1[i][j]);
                int c2 = ty * 24 + 2 * j;
                sAtt[(c2 + 0) * ALD + tx * 4 + i] = p.x * S[i];
                sAtt[(c2 + 1) * ALD + tx * 4 + i] = p.y * S[i];
            }

        // ---------- GEMM2: fq_new[t][c1] = sum_c2 FQ[t][c2]*attn[c2][c1] ----------
        // thread: t = wy + 32i (i<7); c1 pairs {2cx,2cx+1} and {16+2cx,16+2cx+1}
        ull acc2[7][4];
        #pragma unroll
        for (int i = 0; i < 7; ++i)
            #pragma unroll
            for (int j = 0; j < 4; ++j) acc2[i][j] = 0ull;

        for (int c2b = 0; c2b < C_; c2b += 64) {
            __syncthreads();   // prev-phase compute done (and softmax stores for phase 0)
            // stage FQ K-tile transposed: sStg[c2local][t], 64 rows
            for (int idx = tid; idx < T_ * 16; idx += 256) {
                int t = idx >> 4, g = idx & 15;
                float4 v = FQ4[t * 96 + (c2b >> 2) + g];
                sStg[(4 * g + 0) * LDT + t] = v.x;
                sStg[(4 * g + 1) * LDT + t] = v.y;
                sStg[(4 * g + 2) * LDT + t] = v.z;
                sStg[(4 * g + 3) * LDT + t] = v.w;
            }
            __syncthreads();
            #pragma unroll 4
            for (int k0 = 0; k0 < 64; ++k0) {
                const float* arow = &sAtt[(c2b + k0) * ALD];
                const ulonglong2 b01 = *reinterpret_cast<const ulonglong2*>(&arow[cx * 4]);
                const ulonglong2 b23 = *reinterpret_cast<const ulonglong2*>(&arow[32 + cx * 4]);
                const float* srow = &sStg[k0 * LDT];
                #pragma unroll
                for (int i = 0; i < 7; ++i) {
                    float a = srow[wy + 32 * i];
                    ull av = pk2(a, a);
                    acc2[i][0] = fma2(av, b01.x, acc2[i][0]);
                    acc2[i][1] = fma2(av, b01.y, acc2[i][1]);
                    acc2[i][2] = fma2(av, b23.x, acc2[i][2]);
                    acc2[i][3] = fma2(av, b23.y, acc2[i][3]);
                }
            }
        }

        // ---------- fused cosine epilogue ----------
        #pragma unroll
        for (int i = 0; i < 7; ++i) {
            int t = wy + 32 * i;
            if (t < T_) {   // warp-uniform (warp = 4 consecutive wy)
                float2 p0 = upk2(acc2[i][0]);
                float2 p1 = upk2(acc2[i][1]);
                float2 p2 = upk2(acc2[i][2]);
                float2 p3 = upk2(acc2[i][3]);
                float4 f0 = FS4[t * 96 + ch * 16 + cx];       // c1 = cx*4..+3
                float4 f1 = FS4[t * 96 + ch * 16 + 8 + cx];   // c1 = 32+cx*4..+3
                float nl = p0.x * f0.x + p0.y * f0.y + p1.x * f0.z + p1.y * f0.w
                         + p2.x * f1.x + p2.y * f1.y + p3.x * f1.z + p3.y * f1.w;
                float sl = p0.x * p0.x + p0.y * p0.y + p1.x * p1.x + p1.y * p1.y
                         + p2.x * p2.x + p2.y * p2.y + p3.x * p3.x + p3.y * p3.y;
                #pragma unroll
                for (int o = 1; o < 8; o <<= 1) {
                    nl += __shfl_xor_sync(0xffffffffu, nl, o);
                    sl += __shfl_xor_sync(0xffffffffu, sl, o);
                }
                if (cx == 0) { sNum[t] += nl; sSq[t] += sl; }
            }
        }
        __syncthreads();
    }

    // ---------- top-1 over t, mean over n ----------
    if (wid == 0) {
        float best = -1e30f;
        for (int t = lane; t < T_; t += 32) {
            float den = fmaxf(sqrtf(sSq[t] * sFsn[t]), 1e-8f);
            best = fmaxf(best, sNum[t] / den);
        }
        #pragma unroll
        for (int o = 16; o > 0; o >>= 1) best = fmaxf(best, __shfl_xor_sync(0xffffffffu, best, o));
        if (lane == 0) atomicAdd(&out[b * Q_ + q], best * (1.0f / N_));
    }
}

// prototype-cosine branch + output init
__global__ void tok_cls_init_kernel(const float* __restrict__ XQ,
                                    const float* __restrict__ XS,
                                    float* __restrict__ out)
{
    int gtid = blockIdx.x * blockDim.x + threadIdx.x;
    if (gtid < B_ * Q_) out[gtid] = 0.f;
    int w = gtid >> 5;
    int lane = gtid & 31;
    if (w >= B_ * Q_ * N_) return;
    int n = w % N_;
    int bq = w / N_;
    int q = bq % Q_;
    int b = bq / Q_;
    const float* xq = XQ + (size_t)(b * Q_ + q) * D_;
    const float* xs = XS + (size_t)(b * N_ + n) * D_;
    float dot = 0.f, nq = 0.f, ns = 0.f;
    for (int d = lane; d < D_; d += 32) {
        float a = xq[d], c = xs[d];
        dot = fmaf(a, c, dot);
        nq  = fmaf(a, a, nq);
        ns  = fmaf(c, c, ns);
    }
    #pragma unroll
    for (int o = 16; o > 0; o >>= 1) {
        dot += __shfl_xor_sync(0xffffffffu, dot, o);
        nq  += __shfl_xor_sync(0xffffffffu, nq, o);
        ns  += __shfl_xor_sync(0xffffffffu, ns, o);
    }
    if (lane == 0) {
        float denom = fmaxf(sqrtf(nq), 1e-12f) * fmaxf(sqrtf(ns), 1e-12f);
        out[B_ * Q_ + w] = 10.0f * dot / denom;
    }
}

extern "C" void kernel_launch(void* const* d_in, const int* in_sizes, int n_in,
                              void* d_out, int out_size)
{
    const float* fq = (const float*)d_in[0];
    const float* fs = (const float*)d_in[1];
    const float* xq = (const float*)d_in[2];
    const float* xs = (const float*)d_in[3];
    float* out = (float*)d_out;

    cudaFuncSetAttribute(tok_main_kernel,
                         cudaFuncAttributeMaxDynamicSharedMemorySize, SMEM_BYTES);

    tok_cls_init_kernel<<<(B_ * Q_ * N_ * 32 + 255) / 256, 256>>>(xq, xs, out);
    dim3 grid(N_, Q_, B_);
    tok_main_kernel<<<grid, 256, SMEM_BYTES>>>(fq, fs, out);
}

// round 8
// speedup vs baseline: 2.0563x; 1.0969x over previous
#include <cuda_runtime.h>
#include <math.h>

namespace {
constexpr int B_ = 2, Q_ = 75, N_ = 5, T_ = 196, C_ = 384, D_ = 384;
constexpr int CHUNK = 64;               // c1 chunk
constexpr int NCH = C_ / CHUNK;         // 6
constexpr int ALD = 68;                 // attn row stride [c2][c1local]
constexpr int LDT = 211;                // GEMM2 FQ^T staging row stride (odd)
constexpr int BQN = B_ * Q_ * N_;       // 750
constexpr float SCALE = 1.0f / 14.0f;

// smem layout (floats)
constexpr int OFF_ATT = 0;                      // [384][ALD]
constexpr int OFF_FQ  = OFF_ATT + C_ * ALD;     // [196][64]
constexpr int OFF_STG = OFF_FQ + T_ * CHUNK;    // 64 x LDT
constexpr int OFF_RED = OFF_STG + 64 * LDT;     // [64][17]
constexpr int SMEM_FLOATS = OFF_RED + 64 * 17;
constexpr int SMEM_BYTES = SMEM_FLOATS * 4;     // ~213 KB
}

// cross-chunk partials: written exactly once per slot, no zeroing needed
__device__ float gNum[NCH][BQN][T_];
__device__ float gSq [NCH][BQN][T_];
__device__ float gFsn[B_ * N_ * T_];

typedef unsigned long long ull;

__device__ __forceinline__ ull pk2(float lo, float hi) {
    ull r; asm("mov.b64 %0, {%1, %2};" : "=l"(r) : "f"(lo), "f"(hi)); return r;
}
__device__ __forceinline__ float2 upk2(ull v) {
    float2 r; asm("mov.b64 {%0, %1}, %2;" : "=f"(r.x), "=f"(r.y) : "l"(v)); return r;
}
__device__ __forceinline__ ull fma2(ull a, ull b, ull c) {
    ull d; asm("fma.rn.f32x2 %0, %1, %2, %3;" : "=l"(d) : "l"(a), "l"(b), "l"(c)); return d;
}

// One CTA per (b,q,n,ch). 256 threads. grid = (NCH*N, Q, B) -> 4500 CTAs.
__global__ void __launch_bounds__(256, 1)
tok_main_kernel(const float* __restrict__ FQg,
                const float* __restrict__ FSg)
{
    extern __shared__ float sm[];
    float* sAtt = sm + OFF_ATT;
    float* sFQ  = sm + OFF_FQ;
    float* sStg = sm + OFF_STG;
    float* sRed = sm + OFF_RED;

    const int n = blockIdx.x % N_, ch = blockIdx.x / N_;
    const int q = blockIdx.y, b = blockIdx.z;
    const int bqn = (b * Q_ + q) * N_ + n;
    const int tid = threadIdx.x;
    const int tx = tid & 15, ty = tid >> 4;   // GEMM1 / softmax layout
    const int cx = tid & 7,  wy = tid >> 3;   // GEMM2 / epilogue layout

    const float* FQ = FQg + (size_t)(b * Q_ + q) * T_ * C_;
    const float* FS = FSg + (size_t)(b * N_ + n) * T_ * C_;
    const float4* FQ4 = reinterpret_cast<const float4*>(FQ);
    const float4* FS4 = reinterpret_cast<const float4*>(FS);

    // ---------- stage FQ chunk columns: sFQ[t][64], t < 196 ----------
    for (int idx = tid; idx < T_ * 16; idx += 256) {
        int t = idx >> 4, c4 = idx & 15;
        float4 v = FQ4[t * 96 + ch * 16 + c4];
        *reinterpret_cast<float4*>(&sFQ[t * 64 + c4 * 4]) = v;
    }
    __syncthreads();

    // ---------- GEMM1: attn logits; b read straight from global (L2) ----------
    // thread (tx,ty): c1 = tx*4+i (i<4), c2 = ty*24 + 2j{,+1} (j<12)
    ull acc1[4][12];
    #pragma unroll
    for (int i = 0; i < 4; ++i)
        #pragma unroll
        for (int j = 0; j < 12; ++j) acc1[i][j] = 0ull;

    {
        const ulonglong2* fsb = reinterpret_cast<const ulonglong2*>(FS) + ty * 6;
        #pragma unroll 4
        for (int k = 0; k < T_; ++k) {
            ulonglong2 b0 = fsb[k * 96 + 0];
            ulonglong2 b1 = fsb[k * 96 + 1];
            ulonglong2 b2 = fsb[k * 96 + 2];
            ulonglong2 b3 = fsb[k * 96 + 3];
            ulonglong2 b4 = fsb[k * 96 + 4];
            ulonglong2 b5 = fsb[k * 96 + 5];
            float4 a4 = *reinterpret_cast<const float4*>(&sFQ[k * 64 + tx * 4]);
            ull a_[4];
            a_[0] = pk2(a4.x, a4.x); a_[1] = pk2(a4.y, a4.y);
            a_[2] = pk2(a4.z, a4.z); a_[3] = pk2(a4.w, a4.w);
            #pragma unroll
            for (int i = 0; i < 4; ++i) {
                acc1[i][0]  = fma2(a_[i], b0.x, acc1[i][0]);
                acc1[i][1]  = fma2(a_[i], b0.y, acc1[i][1]);
                acc1[i][2]  = fma2(a_[i], b1.x, acc1[i][2]);
                acc1[i][3]  = fma2(a_[i], b1.y, acc1[i][3]);
                acc1[i][4]  = fma2(a_[i], b2.x, acc1[i][4]);
                acc1[i][5]  = fma2(a_[i], b2.y, acc1[i][5]);
                acc1[i][6]  = fma2(a_[i], b3.x, acc1[i][6]);
                acc1[i][7]  = fma2(a_[i], b3.y, acc1[i][7]);
                acc1[i][8]  = fma2(a_[i], b4.x, acc1[i][8]);
                acc1[i][9]  = fma2(a_[i], b4.y, acc1[i][9]);
                acc1[i][10] = fma2(a_[i], b5.x, acc1[i][10]);
                acc1[i][11] = fma2(a_[i], b5.y, acc1[i][11]);
            }
        }
    }

    // ---------- softmax over c2, in registers ----------
    float M[4], S[4];
    #pragma unroll
    for (int i = 0; i < 4; ++i) {
        float m = -1e30f;
        #pragma unroll
        for (int j = 0; j < 12; ++j) {
            float2 p = upk2(acc1[i][j]);
            m = fmaxf(m, fmaxf(p.x, p.y));
        }
        sRed[(tx * 4 + i) * 17 + ty] = m * SCALE;
    }
    __syncthreads();
    #pragma unroll
    for (int i = 0; i < 4; ++i) {
        float m = -1e30f;
        #pragma unroll
        for (int u = 0; u < 16; ++u) m = fmaxf(m, sRed[(tx * 4 + i) * 17 + u]);
        M[i] = m;
    }
    __syncthreads();
    #pragma unroll
    for (int i = 0; i < 4; ++i) {
        float s = 0.f;
        #pragma unroll
        for (int j = 0; j < 12; ++j) {
            float2 p = upk2(acc1[i][j]);
            float e0 = __expf(fmaf(p.x, SCALE, -M[i]));
            float e1 = __expf(fmaf(p.y, SCALE, -M[i]));
            s += e0 + e1;
            acc1[i][j] = pk2(e0, e1);   // cache exp values
        }
        sRed[(tx * 4 + i) * 17 + ty] = s;
    }
    __syncthreads();
    #pragma unroll
    for (int i = 0; i < 4; ++i) {
        float s = 0.f;
        #pragma unroll
        for (int u = 0; u < 16; ++u) s += sRed[(tx * 4 + i) * 17 + u];
        S[i] = 1.f / s;
    }
    // normalized store (transposed scatter): sAtt[c2][c1]
    #pragma unroll
    for (int i = 0; i < 4; ++i)
        #pragma unroll
        for (int j = 0; j < 12; ++j) {
            float2 p = upk2(acc1[i][j]);
            int c2 = ty * 24 + 2 * j;
            sAtt[(c2 + 0) * ALD + tx * 4 + i] = p.x * S[i];
            sAtt[(c2 + 1) * ALD + tx * 4 + i] = p.y * S[i];
        }

    // ---------- GEMM2: fq_new[t][c1] = sum_c2 FQ[t][c2]*attn[c2][c1] ----------
    // thread: t = wy + 32i (i<7); c1 pairs {2cx,2cx+1} and {16+2cx,16+2cx+1}
    ull acc2[7][4];
    #pragma unroll
    for (int i = 0; i < 7; ++i)
        #pragma unroll
        for (int j = 0; j < 4; ++j) acc2[i][j] = 0ull;

    for (int c2b = 0; c2b < C_; c2b += 64) {
        __syncthreads();   // prev-phase compute done (and softmax stores for phase 0)
        for (int idx = tid; idx < T_ * 16; idx += 256) {
            int t = idx >> 4, g = idx & 15;
            float4 v = FQ4[t * 96 + (c2b >> 2) + g];
            sStg[(4 * g + 0) * LDT + t] = v.x;
            sStg[(4 * g + 1) * LDT + t] = v.y;
            sStg[(4 * g + 2) * LDT + t] = v.z;
            sStg[(4 * g + 3) * LDT + t] = v.w;
        }
        __syncthreads();
        #pragma unroll 4
        for (int k0 = 0; k0 < 64; ++k0) {
            const float* arow = &sAtt[(c2b + k0) * ALD];
            const ulonglong2 b01 = *reinterpret_cast<const ulonglong2*>(&arow[cx * 4]);
            const ulonglong2 b23 = *reinterpret_cast<const ulonglong2*>(&arow[32 + cx * 4]);
            const float* srow = &sStg[k0 * LDT];
            #pragma unroll
            for (int i = 0; i < 7; ++i) {
                float a = srow[wy + 32 * i];
                ull av = pk2(a, a);
                acc2[i][0] = fma2(av, b01.x, acc2[i][0]);
                acc2[i][1] = fma2(av, b01.y, acc2[i][1]);
                acc2[i][2] = fma2(av, b23.x, acc2[i][2]);
                acc2[i][3] = fma2(av, b23.y, acc2[i][3]);
            }
        }
    }

    // ---------- fused cosine epilogue: write chunk partials ----------
    #pragma unroll
    for (int i = 0; i < 7; ++i) {
        int t = wy + 32 * i;
        if (t < T_) {   // warp-uniform (warp = 4 consecutive wy)
            float2 p0 = upk2(acc2[i][0]);
            float2 p1 = upk2(acc2[i][1]);
            float2 p2 = upk2(acc2[i][2]);
            float2 p3 = upk2(acc2[i][3]);
            float4 f0 = FS4[t * 96 + ch * 16 + cx];       // c1 = cx*4..+3
            float4 f1 = FS4[t * 96 + ch * 16 + 8 + cx];   // c1 = 32+cx*4..+3
            float nl = p0.x * f0.x + p0.y * f0.y + p1.x * f0.z + p1.y * f0.w
                     + p2.x * f1.x + p2.y * f1.y + p3.x * f1.z + p3.y * f1.w;
            float sl = p0.x * p0.x + p0.y * p0.y + p1.x * p1.x + p1.y * p1.y
                     + p2.x * p2.x + p2.y * p2.y + p3.x * p3.x + p3.y * p3.y;
            #pragma unroll
            for (int o = 1; o < 8; o <<= 1) {
                nl += __shfl_xor_sync(0xffffffffu, nl, o);
                sl += __shfl_xor_sync(0xffffffffu, sl, o);
            }
            if (cx == 0) {
                gNum[ch][bqn][t] = nl;
                gSq [ch][bqn][t] = sl;
            }
        }
    }
}

// prep: zero logits slice, cls branch, FS row norms
__global__ void tok_prep_kernel(const float* __restrict__ FSg,
                                const float* __restrict__ XQ,
                                const float* __restrict__ XS,
                                float* __restrict__ out)
{
    int gtid = blockIdx.x * blockDim.x + threadIdx.x;
    if (gtid < B_ * Q_) out[gtid] = 0.f;
    int w = gtid >> 5;
    int lane = gtid & 31;
    if (w < BQN) {
        // cls[b,q,n] = 10 * <xq_hat, xs_hat>
        int n = w % N_;
        int bq = w / N_;
        int q = bq % Q_;
        int b = bq / Q_;
        const float* xq = XQ + (size_t)(b * Q_ + q) * D_;
        const float* xs = XS + (size_t)(b * N_ + n) * D_;
        float dot = 0.f, nq = 0.f, ns = 0.f;
        for (int d = lane; d < D_; d += 32) {
            float a = xq[d], c = xs[d];
            dot = fmaf(a, c, dot);
            nq  = fmaf(a, a, nq);
            ns  = fmaf(c, c, ns);
        }
        #pragma unroll
        for (int o = 16; o > 0; o >>= 1) {
            dot += __shfl_xor_sync(0xffffffffu, dot, o);
            nq  += __shfl_xor_sync(0xffffffffu, nq, o);
            ns  += __shfl_xor_sync(0xffffffffu, ns, o);
        }
        if (lane == 0) {
            float denom = fmaxf(sqrtf(nq), 1e-12f) * fmaxf(sqrtf(ns), 1e-12f);
            out[B_ * Q_ + w] = 10.0f * dot / denom;
        }
    } else if (w < BQN + B_ * N_ * T_) {
        // gFsn[b*N+n][t] = ||FS[b,n,t,:]||^2  (FS rows are contiguous)
        int r = w - BQN;
        const float* row = FSg + (size_t)r * C_;
        float s = 0.f;
        for (int c = lane; c < C_; c += 32) { float v = row[c]; s = fmaf(v, v, s); }
        #pragma unroll
        for (int o = 16; o > 0; o >>= 1) s += __shfl_xor_sync(0xffffffffu, s, o);
        if (lane == 0) gFsn[r] = s;
    }
}

// reduce: cosine, top-1 over t, mean over n
__global__ void tok_reduce_kernel(float* __restrict__ out)
{
    int w = (blockIdx.x * blockDim.x + threadIdx.x) >> 5;
    int lane = threadIdx.x & 31;
    if (w >= BQN) return;
    int n = w % N_;
    int bq = w / N_;
    int q = bq % Q_;
    int b = bq / Q_;
    const float* fsn = &gFsn[(b * N_ + n) * T_];
    float best = -1e30f;
    for (int t = lane; t < T_; t += 32) {
        float num = 0.f, sq = 0.f;
        #pragma unroll
        for (int ch = 0; ch < NCH; ++ch) {
            num += gNum[ch][w][t];
            sq  += gSq [ch][w][t];
        }
        float den = fmaxf(sqrtf(sq * fsn[t]), 1e-8f);
        best = fmaxf(best, num / den);
    }
    #pragma unroll
    for (int o = 16; o > 0; o >>= 1) best = fmaxf(best, __shfl_xor_sync(0xffffffffu, best, o));
    if (lane == 0) atomicAdd(&out[b * Q_ + q], best * (1.0f / N_));
}

extern "C" void kernel_launch(void* const* d_in, const int* in_sizes, int n_in,
                              void* d_out, int out_size)
{
    const float* fq = (const float*)d_in[0];
    const float* fs = (const float*)d_in[1];
    const float* xq = (const float*)d_in[2];
    const float* xs = (const float*)d_in[3];
    float* out = (float*)d_out;

    cudaFuncSetAttribute(tok_main_kernel,
                         cudaFuncAttributeMaxDynamicSharedMemorySize, SMEM_BYTES);

    // prep needs BQN + B*N*T = 750 + 1960 = 2710 warps
    int prep_threads = (BQN + B_ * N_ * T_) * 32;
    tok_prep_kernel<<<(prep_threads + 255) / 256, 256>>>(fs, xq, xs, out);
    dim3 grid(NCH * N_, Q_, B_);
    tok_main_kernel<<<grid, 256, SMEM_BYTES>>>(fq, fs);
    tok_reduce_kernel<<<(BQN * 32 + 255) / 256, 256>>>(out);
}